// round 10
// baseline (speedup 1.0000x reference)
#include <cuda_runtime.h>
#include <cuda_bf16.h>
#include <cstdint>
#include <cstddef>

#define SEQ    512
#define NBAT   256
#define IN_DIM 256
#define HID    1024
#define NCLS   128

// ---------------- scratch (no allocation allowed -> device globals) ----------
static __device__ float d_xfp[(size_t)SEQ * NBAT * HID];  // bf + emb@Wfx^T
static __device__ float d_xip[(size_t)SEQ * NBAT * HID];  // bi + emb@Wix^T
static __device__ float d_g  [(size_t)SEQ * NBAT * HID];  // sigmoid(bc + emb@Wcx^T)
static __device__ float d_c0 [NBAT * HID];   // fp32 c_512 (written t=511)
static __device__ float d_c1 [NBAT * HID];   // fp32 c_511 (written t=510)
static __device__ __nv_bfloat16 d_cb0[NBAT * HID];  // bf16 c ping-pong
static __device__ __nv_bfloat16 d_cb1[NBAT * HID];
static __device__ float d_hT [NBAT * HID];
static __device__ int   d_bar[4];            // per-batch-group step barrier
// rounded weights
static __device__ __nv_bfloat16 d_Wfh_b[HID * HID];
static __device__ __nv_bfloat16 d_Wih_b[HID * HID];
static __device__ float d_Wfx_r[HID * IN_DIM];
static __device__ float d_Wix_r[HID * IN_DIM];
static __device__ float d_Wcx_r[HID * IN_DIM];
static __device__ float d_emb_r[NCLS * IN_DIM];

__device__ __forceinline__ float sigf(float x) { return 1.0f / (1.0f + __expf(-x)); }
__device__ __forceinline__ float tf32r(float x) {
    uint32_t r;
    asm("cvt.rna.tf32.f32 %0, %1;" : "=r"(r) : "f"(x));
    return __uint_as_float(r);
}
__device__ __forceinline__ int ld_acq(const int* p) {
    int v;
    asm volatile("ld.acquire.gpu.b32 %0, [%1];" : "=r"(v) : "l"(p));
    return v;
}

// ---------------- mma / ldmatrix / cp.async helpers --------------------------
__device__ __forceinline__ void mma_tf32_8(float* c, const uint32_t* a, const uint32_t* b) {
    asm volatile(
        "mma.sync.aligned.m16n8k8.row.col.f32.tf32.tf32.f32 "
        "{%0,%1,%2,%3}, {%4,%5,%6,%7}, {%8,%9}, {%0,%1,%2,%3};"
        : "+f"(c[0]), "+f"(c[1]), "+f"(c[2]), "+f"(c[3])
        : "r"(a[0]), "r"(a[1]), "r"(a[2]), "r"(a[3]), "r"(b[0]), "r"(b[1]));
}
__device__ __forceinline__ void mma_bf16_16(float* c, const uint32_t* a,
                                            uint32_t b0, uint32_t b1) {
    asm volatile(
        "mma.sync.aligned.m16n8k16.row.col.f32.bf16.bf16.f32 "
        "{%0,%1,%2,%3}, {%4,%5,%6,%7}, {%8,%9}, {%0,%1,%2,%3};"
        : "+f"(c[0]), "+f"(c[1]), "+f"(c[2]), "+f"(c[3])
        : "r"(a[0]), "r"(a[1]), "r"(a[2]), "r"(a[3]), "r"(b0), "r"(b1));
}
__device__ __forceinline__ void ldmx4(uint32_t* r, uint32_t addr) {
    asm volatile("ldmatrix.sync.aligned.m8n8.x4.shared.b16 {%0,%1,%2,%3}, [%4];"
        : "=r"(r[0]), "=r"(r[1]), "=r"(r[2]), "=r"(r[3]) : "r"(addr));
}
#define CP16(d, s)  asm volatile("cp.async.cg.shared.global [%0], [%1], 16;" :: "r"(d), "l"(s) : "memory")
#define CP_COMMIT() asm volatile("cp.async.commit_group;" ::: "memory")
#define CP_WAIT2()  asm volatile("cp.async.wait_group 2;" ::: "memory")
#define CP_WAIT1()  asm volatile("cp.async.wait_group 1;" ::: "memory")
#define CP_WAIT0()  asm volatile("cp.async.wait_group 0;" ::: "memory")

__device__ __forceinline__ uint32_t smem_u32(const void* p) {
    uint32_t a;
    asm("{ .reg .u64 t; cvta.to.shared.u64 t, %1; cvt.u32.u64 %0, t; }" : "=r"(a) : "l"(p));
    return a;
}

// ---------------- fused rounding: Wfh/Wih -> bf16, x-weights/emb -> tf32 ----
__global__ void __launch_bounds__(256) round_all(
    const float* __restrict__ Wfh, const float* __restrict__ Wih,
    const float* __restrict__ Wfx, const float* __restrict__ Wix,
    const float* __restrict__ Wcx, const float* __restrict__ emb)
{
    int i = blockIdx.x * 256 + threadIdx.x;
    if (i < 1048576) { d_Wfh_b[i] = __float2bfloat16_rn(Wfh[i]); return; }
    i -= 1048576;
    if (i < 1048576) { d_Wih_b[i] = __float2bfloat16_rn(Wih[i]); return; }
    i -= 1048576;
    if (i < 262144) { d_Wfx_r[i] = tf32r(Wfx[i]); return; }
    i -= 262144;
    if (i < 262144) { d_Wix_r[i] = tf32r(Wix[i]); return; }
    i -= 262144;
    if (i < 262144) { d_Wcx_r[i] = tf32r(Wcx[i]); return; }
    i -= 262144;
    if (i < 32768) { d_emb_r[i] = tf32r(emb[i]); }
}

// ---------------- init: bf16 c = 0, barrier counters = 0 ---------------------
__global__ void zero_c_kernel() {
    int i = blockIdx.x * 256 + threadIdx.x;
    d_cb0[i] = __float2bfloat16_rn(0.0f);
    if (i < 4) d_bar[i] = 0;
}

// ===================== Phase A: 3-gate tf32 mma GEMM (unchanged) ============
#define PA_SMEM (55808)

__global__ void __launch_bounds__(256) phaseA_mma(
    const int* __restrict__ x,
    const float* __restrict__ bfv, const float* __restrict__ biv, const float* __restrict__ bcv)
{
    extern __shared__ __align__(16) char dsm[];
    float (*As)[128][36] = reinterpret_cast<float(*)[128][36]>(dsm);
    float (*Bs)[64][36]  = reinterpret_cast<float(*)[64][36]>(dsm + 36864);
    int* idx = reinterpret_cast<int*>(dsm + 55296);

    const int tid  = threadIdx.x;
    const int wid  = tid >> 5, lane = tid & 31;
    const int m0   = blockIdx.x * 128;
    const int n0   = blockIdx.y * 64;
    const int g    = blockIdx.z;
    const int mbase = (wid >> 1) * 32;
    const int nbase = (wid & 1) * 32;

    const float* __restrict__ Wp =
        (g == 0) ? d_Wfx_r : (g == 1) ? d_Wix_r : d_Wcx_r;
    const float* __restrict__ bp = (g == 0) ? bfv : (g == 1) ? biv : bcv;
    float* __restrict__ outp = (g == 0) ? d_xfp : (g == 1) ? d_xip : d_g;

    if (tid < 128) {
        int m = m0 + tid;
        idx[tid] = x[(m & 255) * SEQ + (m >> 8)];
    }
    __syncthreads();

    const uint32_t sA = smem_u32(As);
    const uint32_t sB = smem_u32(Bs);

    auto load_chunk = [&](int c, int buf) {
        const int k0 = c * 32;
#pragma unroll
        for (int i = 0; i < 4; i++) {
            int ch  = tid + i * 256;
            int row = ch >> 3, c16 = ch & 7;
            uint32_t dst = sA + (uint32_t)buf * 18432u + (uint32_t)row * 144u + (uint32_t)c16 * 16u;
            CP16(dst, d_emb_r + (size_t)idx[row] * IN_DIM + k0 + c16 * 4);
        }
#pragma unroll
        for (int i = 0; i < 2; i++) {
            int ch  = tid + i * 256;
            int row = ch >> 3, c16 = ch & 7;
            uint32_t dst = sB + (uint32_t)buf * 9216u + (uint32_t)row * 144u + (uint32_t)c16 * 16u;
            CP16(dst, Wp + (size_t)(n0 + row) * IN_DIM + k0 + c16 * 4);
        }
        CP_COMMIT();
    };

    float acc[2][4][4];
#pragma unroll
    for (int i = 0; i < 2; i++)
#pragma unroll
        for (int j = 0; j < 4; j++)
#pragma unroll
            for (int r = 0; r < 4; r++) acc[i][j][r] = 0.0f;

    load_chunk(0, 0);
    for (int c = 0; c < 8; c++) {
        if (c + 1 < 8) load_chunk(c + 1, (c + 1) & 1);
        if (c + 1 < 8) { CP_WAIT1(); } else { CP_WAIT0(); }
        __syncthreads();
        const int buf = c & 1;
#pragma unroll
        for (int kk = 0; kk < 4; kk++) {
            const int kc = kk * 8 + (lane & 3);
            uint32_t a[2][4], b[4][2];
#pragma unroll
            for (int mt = 0; mt < 2; mt++) {
                int r = mbase + mt * 16 + (lane >> 2);
                a[mt][0] = __float_as_uint(As[buf][r][kc]);
                a[mt][1] = __float_as_uint(As[buf][r + 8][kc]);
                a[mt][2] = __float_as_uint(As[buf][r][kc + 4]);
                a[mt][3] = __float_as_uint(As[buf][r + 8][kc + 4]);
            }
#pragma unroll
            for (int nt = 0; nt < 4; nt++) {
                int n = nbase + nt * 8 + (lane >> 2);
                b[nt][0] = __float_as_uint(Bs[buf][n][kc]);
                b[nt][1] = __float_as_uint(Bs[buf][n][kc + 4]);
            }
#pragma unroll
            for (int mt = 0; mt < 2; mt++)
#pragma unroll
                for (int nt = 0; nt < 4; nt++) mma_tf32_8(acc[mt][nt], a[mt], b[nt]);
        }
        __syncthreads();
    }

#pragma unroll
    for (int mt = 0; mt < 2; mt++) {
        int mA = m0 + mbase + mt * 16 + (lane >> 2);
#pragma unroll
        for (int nt = 0; nt < 4; nt++) {
            int col = n0 + nbase + nt * 8 + (lane & 3) * 2;
            float b0v = bp[col], b1v = bp[col + 1];
            float2 lo, hi;
            lo.x = acc[mt][nt][0] + b0v; lo.y = acc[mt][nt][1] + b1v;
            hi.x = acc[mt][nt][2] + b0v; hi.y = acc[mt][nt][3] + b1v;
            if (g == 2) { lo.x = sigf(lo.x); lo.y = sigf(lo.y); hi.x = sigf(hi.x); hi.y = sigf(hi.y); }
            *(float2*)(outp + (size_t)mA * HID + col) = lo;
            *(float2*)(outp + (size_t)(mA + 8) * HID + col) = hi;
        }
    }
}

// ===================== Persistent recurrence: all 512 steps =================
// Grid 128 = 4 batch-groups x 32 hidden-groups, 1 CTA/SM, all resident.
// Weights (2 gates x 32 hid x 1024 K bf16 = 128KB) resident in SMEM per CTA.
// Exact fp32 c in registers (8/thread); bf16 c ping-pongs through global.
// Per-step inter-CTA sync: per-batch-group atomic counter barrier.
// SMEM: W 64 rows x 2064B = 132096 | A stages 4 x (64 x 144B) = 36864.
// Epilogue pre[2][64][34] f32 (17408B) aliases the A stages.
#define WROW      2064
#define WSM_BYTES (64 * WROW)
#define AST_BYTES (64 * 144)
#define PS_SMEM   (WSM_BYTES + 4 * AST_BYTES)   // 168960

__global__ void __launch_bounds__(256) persist_step()
{
    extern __shared__ __align__(16) char dsm[];
    float (*pre)[64][34] = reinterpret_cast<float(*)[64][34]>(dsm + WSM_BYTES);

    const int tid = threadIdx.x;
    const int wid = tid >> 5, lane = tid & 31;
    const int bgr = blockIdx.x >> 5;        // batch group 0..3
    const int ng  = blockIdx.x & 31;        // hidden group 0..31
    const int b0  = bgr * 64;
    const int n0  = ng * 32;
    const int g   = wid >> 2;
    const int wq  = wid & 3;
    const int mbase = (wq >> 1) * 32;
    const int nwarp = (wq & 1) * 16;

    const uint32_t sW = smem_u32(dsm);
    const uint32_t sA = sW + WSM_BYTES;

    // ---- load weights once: 64 rows (gate*32+hid) x 2048B ----
#pragma unroll
    for (int i = 0; i < 32; i++) {
        int ch = tid + i * 256;             // 0..8191
        int row = ch >> 7, c16 = ch & 127;
        const __nv_bfloat16* src = ((row >> 5) ? d_Wih_b : d_Wfh_b)
            + (size_t)(n0 + (row & 31)) * HID + c16 * 8;
        CP16(sW + (uint32_t)row * WROW + (uint32_t)c16 * 16u, src);
    }
    CP_COMMIT(); CP_WAIT0();
    __syncthreads();

    float c_reg[8];
#pragma unroll
    for (int j = 0; j < 8; j++) c_reg[j] = 0.0f;

    const int brow0 = g * 32 + nwarp;
    const uint32_t lquad = lane & 15;
    const uint32_t lhalf = (lane >> 4) * 16u;
    const int em  = tid >> 2;               // epilogue row 0..63
    const int enb = (tid & 3) * 8;          // epilogue col base

    for (int t = 0; t < SEQ; t++) {
        if (t > 0) {
            if (tid == 0) { while (ld_acq(&d_bar[bgr]) < 32 * t) {} }
            __syncthreads();
        }
        const __nv_bfloat16* __restrict__ cbin  = (t & 1) ? d_cb1 : d_cb0;
        __nv_bfloat16* __restrict__       coutb = (t & 1) ? d_cb0 : d_cb1;
        const size_t toff = (size_t)t * (NBAT * HID);

        // prefetch x-parts for epilogue (independent of c)
        const size_t goff = (size_t)(b0 + em) * HID + n0 + enb;
        const float4 xf0 = *(const float4*)(d_xfp + toff + goff);
        const float4 xf1 = *(const float4*)(d_xfp + toff + goff + 4);
        const float4 xi0 = *(const float4*)(d_xip + toff + goff);
        const float4 xi1 = *(const float4*)(d_xip + toff + goff + 4);
        const float4 gg0 = *(const float4*)(d_g + toff + goff);
        const float4 gg1 = *(const float4*)(d_g + toff + goff + 4);

        auto load_chunk = [&](int c, int st) {
            const int k0 = c * 64;
#pragma unroll
            for (int i = 0; i < 2; i++) {
                int ch = tid + i * 256;      // 0..511
                int row = ch >> 3, c16 = ch & 7;
                CP16(sA + (uint32_t)st * AST_BYTES + (uint32_t)row * 144u + (uint32_t)c16 * 16u,
                     cbin + (size_t)(b0 + row) * HID + k0 + c16 * 8);
            }
            CP_COMMIT();
        };

        float acc[2][2][4];
#pragma unroll
        for (int i = 0; i < 2; i++)
#pragma unroll
            for (int j = 0; j < 2; j++)
#pragma unroll
                for (int r = 0; r < 4; r++) acc[i][j][r] = 0.0f;

        load_chunk(0, 0); load_chunk(1, 1); load_chunk(2, 2);

        for (int c = 0; c < 16; c++) {
            if (c <= 13)      { CP_WAIT2(); }
            else if (c == 14) { CP_WAIT1(); }
            else              { CP_WAIT0(); }
            __syncthreads();
            if (c + 3 < 16) load_chunk(c + 3, (c + 3) & 3);

            const uint32_t stA = sA + (uint32_t)(c & 3) * AST_BYTES;
            const uint32_t wcol = (uint32_t)c * 128u;
#pragma unroll
            for (int kk = 0; kk < 4; kk++) {
                uint32_t a[2][4], b[4];
#pragma unroll
                for (int mt = 0; mt < 2; mt++) {
                    ldmx4(a[mt], stA + (uint32_t)(mbase + mt * 16 + lquad) * 144u
                                 + (uint32_t)kk * 32u + lhalf);
                }
                ldmx4(b, sW + (uint32_t)(brow0 + lquad) * WROW + wcol
                         + (uint32_t)kk * 32u + lhalf);
#pragma unroll
                for (int mt = 0; mt < 2; mt++) {
                    mma_bf16_16(acc[mt][0], a[mt], b[0], b[2]);
                    mma_bf16_16(acc[mt][1], a[mt], b[1], b[3]);
                }
            }
        }
        __syncthreads();   // all tile reads done before aliasing pre over A stages

        // stage pre-activations to shared
#pragma unroll
        for (int mt = 0; mt < 2; mt++) {
            int m = mbase + mt * 16 + (lane >> 2);
#pragma unroll
            for (int nt = 0; nt < 2; nt++) {
                int n = nwarp + nt * 8 + (lane & 3) * 2;
                pre[g][m][n]         = acc[mt][nt][0];
                pre[g][m][n + 1]     = acc[mt][nt][1];
                pre[g][m + 8][n]     = acc[mt][nt][2];
                pre[g][m + 8][n + 1] = acc[mt][nt][3];
            }
        }
        __syncthreads();

        // pointwise: c_new = g*sig(pre_i + xi) + c*sig(pre_f + xf), c in regs
        {
            float xf[8] = { xf0.x, xf0.y, xf0.z, xf0.w, xf1.x, xf1.y, xf1.z, xf1.w };
            float xi[8] = { xi0.x, xi0.y, xi0.z, xi0.w, xi1.x, xi1.y, xi1.z, xi1.w };
            float gv[8] = { gg0.x, gg0.y, gg0.z, gg0.w, gg1.x, gg1.y, gg1.z, gg1.w };
            __nv_bfloat16 cb[8];
#pragma unroll
            for (int j = 0; j < 8; j++) {
                float f  = sigf(pre[0][em][enb + j] + xf[j]);
                float ii = sigf(pre[1][em][enb + j] + xi[j]);
                float cn = gv[j] * ii + c_reg[j] * f;
                c_reg[j] = cn;
                cb[j] = __float2bfloat16_rn(cn);
            }
            *(uint4*)(coutb + goff) = *(const uint4*)cb;     // 8 bf16 = 16B
            if (t >= SEQ - 2) {
                float* cf = (t & 1) ? d_c0 : d_c1;           // t=510->d_c1 (c_511), t=511->d_c0 (c_512)
                *(float4*)(cf + goff)     = make_float4(c_reg[0], c_reg[1], c_reg[2], c_reg[3]);
                *(float4*)(cf + goff + 4) = make_float4(c_reg[4], c_reg[5], c_reg[6], c_reg[7]);
            }
        }
        __threadfence();
        __syncthreads();
        if (t < SEQ - 1 && tid == 0) atomicAdd(&d_bar[bgr], 1);
    }
}

// ---------------- final step o-gate + h (fp32 SIMT, tiny) --------------------
__global__ void __launch_bounds__(256) finalO_kernel(
    const int* __restrict__ x, const float* __restrict__ emb,
    const float* __restrict__ Wox, const float* __restrict__ Woh,
    const float* __restrict__ bo)
{
    __shared__ float As[64][33];
    __shared__ float Bs[64][33];
    __shared__ int   idx[64];
    const int tid = threadIdx.x;
    const int n0 = blockIdx.x * 64;
    const int b0 = blockIdx.y * 64;

    if (tid < 64) idx[tid] = x[(b0 + tid) * SEQ + (SEQ - 1)];
    __syncthreads();

    float acc[4][4];
#pragma unroll
    for (int i = 0; i < 4; i++)
#pragma unroll
        for (int j = 0; j < 4; j++) acc[i][j] = 0.0f;

    const int mt = (tid >> 4) * 4;
    const int nt = (tid & 15) * 4;

    for (int k0 = 0; k0 < HID; k0 += 32) {
#pragma unroll
        for (int i = 0; i < 2; i++) {
            int r  = (tid >> 3) + i * 32;
            int kq = (tid & 7) * 4;
            float4 v = *(const float4*)(d_c1 + (size_t)(b0 + r) * HID + k0 + kq);
            As[r][kq+0]=v.x; As[r][kq+1]=v.y; As[r][kq+2]=v.z; As[r][kq+3]=v.w;
            float4 u = *(const float4*)(Woh + (size_t)(n0 + r) * HID + k0 + kq);
            Bs[r][kq+0]=u.x; Bs[r][kq+1]=u.y; Bs[r][kq+2]=u.z; Bs[r][kq+3]=u.w;
        }
        __syncthreads();
#pragma unroll
        for (int k = 0; k < 32; k++) {
            float a[4], bv[4];
#pragma unroll
            for (int i = 0; i < 4; i++) a[i] = As[mt + i][k];
#pragma unroll
            for (int j = 0; j < 4; j++) bv[j] = Bs[nt + j][k];
#pragma unroll
            for (int i = 0; i < 4; i++)
#pragma unroll
                for (int j = 0; j < 4; j++) acc[i][j] += a[i] * bv[j];
        }
        __syncthreads();
    }
    for (int k0 = 0; k0 < IN_DIM; k0 += 32) {
#pragma unroll
        for (int i = 0; i < 2; i++) {
            int r  = (tid >> 3) + i * 32;
            int kq = (tid & 7) * 4;
            float4 v = *(const float4*)(emb + (size_t)idx[r] * IN_DIM + k0 + kq);
            As[r][kq+0]=v.x; As[r][kq+1]=v.y; As[r][kq+2]=v.z; As[r][kq+3]=v.w;
            float4 u = *(const float4*)(Wox + (size_t)(n0 + r) * IN_DIM + k0 + kq);
            Bs[r][kq+0]=u.x; Bs[r][kq+1]=u.y; Bs[r][kq+2]=u.z; Bs[r][kq+3]=u.w;
        }
        __syncthreads();
#pragma unroll
        for (int k = 0; k < 32; k++) {
            float a[4], bv[4];
#pragma unroll
            for (int i = 0; i < 4; i++) a[i] = As[mt + i][k];
#pragma unroll
            for (int j = 0; j < 4; j++) bv[j] = Bs[nt + j][k];
#pragma unroll
            for (int i = 0; i < 4; i++)
#pragma unroll
                for (int j = 0; j < 4; j++) acc[i][j] += a[i] * bv[j];
        }
        __syncthreads();
    }

#pragma unroll
    for (int i = 0; i < 4; i++) {
        int b = b0 + mt + i;
#pragma unroll
        for (int j = 0; j < 4; j++) {
            int h = n0 + nt + j;
            size_t off = (size_t)b * HID + h;
            float o = sigf(acc[i][j] + bo[h]);
            d_hT[off] = tanhf(d_c0[off]) * o;
        }
    }
}

// ---------------- projection + log_softmax ----------------------------------
__global__ void __launch_bounds__(128) proj_kernel(
    const float* __restrict__ Wph, const float* __restrict__ bp,
    float* __restrict__ out)
{
    const int b = blockIdx.x;
    const int n = threadIdx.x;
    __shared__ float hs[HID];
    for (int k = n; k < HID; k += 128) hs[k] = d_hT[(size_t)b * HID + k];
    __syncthreads();

    const float* w = Wph + (size_t)n * HID;
    float acc = bp[n];
#pragma unroll 8
    for (int k = 0; k < HID; k++) acc += hs[k] * w[k];

    __shared__ float red[128];
    red[n] = acc;
    __syncthreads();
    for (int off = 64; off > 0; off >>= 1) {
        if (n < off) red[n] = fmaxf(red[n], red[n + off]);
        __syncthreads();
    }
    float mx = red[0];
    __syncthreads();
    red[n] = __expf(acc - mx);
    __syncthreads();
    for (int off = 64; off > 0; off >>= 1) {
        if (n < off) red[n] += red[n + off];
        __syncthreads();
    }
    float lse = mx + logf(red[0]);
    out[(size_t)b * NCLS + n] = acc - lse;
}

// ---------------- launch ------------------------------------------------------
extern "C" void kernel_launch(void* const* d_in, const int* in_sizes, int n_in,
                              void* d_out, int out_size)
{
    (void)in_sizes; (void)n_in; (void)out_size;
    const int*   x   = (const int*)  d_in[0];
    const float* emb = (const float*)d_in[1];
    const float* Wcx = (const float*)d_in[2];
    const float* bc  = (const float*)d_in[3];
    const float* Wix = (const float*)d_in[4];
    const float* Wih = (const float*)d_in[5];
    const float* bi  = (const float*)d_in[6];
    const float* Wfx = (const float*)d_in[7];
    const float* Wfh = (const float*)d_in[8];
    const float* bf  = (const float*)d_in[9];
    const float* Wox = (const float*)d_in[10];
    const float* Woh = (const float*)d_in[11];
    const float* bo  = (const float*)d_in[12];
    const float* Wph = (const float*)d_in[13];
    const float* bp  = (const float*)d_in[14];
    float* out = (float*)d_out;

    cudaFuncSetAttribute(phaseA_mma, cudaFuncAttributeMaxDynamicSharedMemorySize, PA_SMEM);
    cudaFuncSetAttribute(persist_step, cudaFuncAttributeMaxDynamicSharedMemorySize, PS_SMEM);

    round_all<<<11392, 256>>>(Wfh, Wih, Wfx, Wix, Wcx, emb);

    phaseA_mma<<<dim3(SEQ * NBAT / 128, HID / 64, 3), 256, PA_SMEM>>>(x, bf, bi, bc);
    zero_c_kernel<<<NBAT * HID / 256, 256>>>();

    persist_step<<<128, 256, PS_SMEM>>>();

    finalO_kernel<<<dim3(HID / 64, NBAT / 64), 256>>>(x, emb, Wox, Woh, bo);
    proj_kernel<<<NBAT, 128>>>(Wph, bp, out);
}

// round 11
// speedup vs baseline: 1.4715x; 1.4715x over previous
#include <cuda_runtime.h>
#include <cuda_bf16.h>
#include <cstdint>
#include <cstddef>

#define SEQ    512
#define NBAT   256
#define IN_DIM 256
#define HID    1024
#define NCLS   128

// ---------------- scratch (no allocation allowed -> device globals) ----------
static __device__ float d_xfp[(size_t)SEQ * NBAT * HID];  // bf + emb@Wfx^T
static __device__ float d_xip[(size_t)SEQ * NBAT * HID];  // bi + emb@Wix^T
static __device__ float d_g  [(size_t)SEQ * NBAT * HID];  // sigmoid(bc + emb@Wcx^T)
static __device__ float d_c0 [NBAT * HID];   // fp32 c_512 (written t=511)
static __device__ float d_c1 [NBAT * HID];   // fp32 c_511 (written t=510)
static __device__ __nv_bfloat16 d_cb0[NBAT * HID];  // bf16 c ping-pong
static __device__ __nv_bfloat16 d_cb1[NBAT * HID];
static __device__ float d_hT [NBAT * HID];
static __device__ int   d_bar[4];            // per-batch-group step barrier
// rounded weights
static __device__ __nv_bfloat16 d_Wfh_b[HID * HID];
static __device__ __nv_bfloat16 d_Wih_b[HID * HID];
static __device__ float d_Wfx_r[HID * IN_DIM];
static __device__ float d_Wix_r[HID * IN_DIM];
static __device__ float d_Wcx_r[HID * IN_DIM];
static __device__ float d_emb_r[NCLS * IN_DIM];

__device__ __forceinline__ float sigf(float x) { return 1.0f / (1.0f + __expf(-x)); }
__device__ __forceinline__ float tf32r(float x) {
    uint32_t r;
    asm("cvt.rna.tf32.f32 %0, %1;" : "=r"(r) : "f"(x));
    return __uint_as_float(r);
}
__device__ __forceinline__ int ld_acq(const int* p) {
    int v;
    asm volatile("ld.acquire.gpu.b32 %0, [%1];" : "=r"(v) : "l"(p));
    return v;
}
__device__ __forceinline__ void red_release_add(int* p, int v) {
    asm volatile("red.release.gpu.global.add.s32 [%0], %1;" :: "l"(p), "r"(v) : "memory");
}

// ---------------- mma / ldmatrix / cp.async helpers --------------------------
__device__ __forceinline__ void mma_tf32_8(float* c, const uint32_t* a, const uint32_t* b) {
    asm volatile(
        "mma.sync.aligned.m16n8k8.row.col.f32.tf32.tf32.f32 "
        "{%0,%1,%2,%3}, {%4,%5,%6,%7}, {%8,%9}, {%0,%1,%2,%3};"
        : "+f"(c[0]), "+f"(c[1]), "+f"(c[2]), "+f"(c[3])
        : "r"(a[0]), "r"(a[1]), "r"(a[2]), "r"(a[3]), "r"(b[0]), "r"(b[1]));
}
__device__ __forceinline__ void mma_bf16_16(float* c, const uint32_t* a,
                                            uint32_t b0, uint32_t b1) {
    asm volatile(
        "mma.sync.aligned.m16n8k16.row.col.f32.bf16.bf16.f32 "
        "{%0,%1,%2,%3}, {%4,%5,%6,%7}, {%8,%9}, {%0,%1,%2,%3};"
        : "+f"(c[0]), "+f"(c[1]), "+f"(c[2]), "+f"(c[3])
        : "r"(a[0]), "r"(a[1]), "r"(a[2]), "r"(a[3]), "r"(b0), "r"(b1));
}
__device__ __forceinline__ void ldmx4(uint32_t* r, uint32_t addr) {
    asm volatile("ldmatrix.sync.aligned.m8n8.x4.shared.b16 {%0,%1,%2,%3}, [%4];"
        : "=r"(r[0]), "=r"(r[1]), "=r"(r[2]), "=r"(r[3]) : "r"(addr));
}
#define CP16(d, s)  asm volatile("cp.async.cg.shared.global [%0], [%1], 16;" :: "r"(d), "l"(s) : "memory")
#define CP_COMMIT() asm volatile("cp.async.commit_group;" ::: "memory")
#define CP_WAIT1()  asm volatile("cp.async.wait_group 1;" ::: "memory")
#define CP_WAIT0()  asm volatile("cp.async.wait_group 0;" ::: "memory")

__device__ __forceinline__ uint32_t smem_u32(const void* p) {
    uint32_t a;
    asm("{ .reg .u64 t; cvta.to.shared.u64 t, %1; cvt.u32.u64 %0, t; }" : "=r"(a) : "l"(p));
    return a;
}

// ---------------- fused rounding: Wfh/Wih -> bf16, x-weights/emb -> tf32 ----
__global__ void __launch_bounds__(256) round_all(
    const float* __restrict__ Wfh, const float* __restrict__ Wih,
    const float* __restrict__ Wfx, const float* __restrict__ Wix,
    const float* __restrict__ Wcx, const float* __restrict__ emb)
{
    int i = blockIdx.x * 256 + threadIdx.x;
    if (i < 1048576) { d_Wfh_b[i] = __float2bfloat16_rn(Wfh[i]); return; }
    i -= 1048576;
    if (i < 1048576) { d_Wih_b[i] = __float2bfloat16_rn(Wih[i]); return; }
    i -= 1048576;
    if (i < 262144) { d_Wfx_r[i] = tf32r(Wfx[i]); return; }
    i -= 262144;
    if (i < 262144) { d_Wix_r[i] = tf32r(Wix[i]); return; }
    i -= 262144;
    if (i < 262144) { d_Wcx_r[i] = tf32r(Wcx[i]); return; }
    i -= 262144;
    if (i < 32768) { d_emb_r[i] = tf32r(emb[i]); }
}

// ---------------- init: bf16 c = 0, barrier counters = 0 ---------------------
__global__ void zero_c_kernel() {
    int i = blockIdx.x * 256 + threadIdx.x;
    d_cb0[i] = __float2bfloat16_rn(0.0f);
    if (i < 4) d_bar[i] = 0;
}

// ===================== Phase A: 3-gate tf32 mma GEMM (unchanged) ============
#define PA_SMEM (55808)

__global__ void __launch_bounds__(256) phaseA_mma(
    const int* __restrict__ x,
    const float* __restrict__ bfv, const float* __restrict__ biv, const float* __restrict__ bcv)
{
    extern __shared__ __align__(16) char dsm[];
    float (*As)[128][36] = reinterpret_cast<float(*)[128][36]>(dsm);
    float (*Bs)[64][36]  = reinterpret_cast<float(*)[64][36]>(dsm + 36864);
    int* idx = reinterpret_cast<int*>(dsm + 55296);

    const int tid  = threadIdx.x;
    const int wid  = tid >> 5, lane = tid & 31;
    const int m0   = blockIdx.x * 128;
    const int n0   = blockIdx.y * 64;
    const int g    = blockIdx.z;
    const int mbase = (wid >> 1) * 32;
    const int nbase = (wid & 1) * 32;

    const float* __restrict__ Wp =
        (g == 0) ? d_Wfx_r : (g == 1) ? d_Wix_r : d_Wcx_r;
    const float* __restrict__ bp = (g == 0) ? bfv : (g == 1) ? biv : bcv;
    float* __restrict__ outp = (g == 0) ? d_xfp : (g == 1) ? d_xip : d_g;

    if (tid < 128) {
        int m = m0 + tid;
        idx[tid] = x[(m & 255) * SEQ + (m >> 8)];
    }
    __syncthreads();

    const uint32_t sA = smem_u32(As);
    const uint32_t sB = smem_u32(Bs);

    auto load_chunk = [&](int c, int buf) {
        const int k0 = c * 32;
#pragma unroll
        for (int i = 0; i < 4; i++) {
            int ch  = tid + i * 256;
            int row = ch >> 3, c16 = ch & 7;
            uint32_t dst = sA + (uint32_t)buf * 18432u + (uint32_t)row * 144u + (uint32_t)c16 * 16u;
            CP16(dst, d_emb_r + (size_t)idx[row] * IN_DIM + k0 + c16 * 4);
        }
#pragma unroll
        for (int i = 0; i < 2; i++) {
            int ch  = tid + i * 256;
            int row = ch >> 3, c16 = ch & 7;
            uint32_t dst = sB + (uint32_t)buf * 9216u + (uint32_t)row * 144u + (uint32_t)c16 * 16u;
            CP16(dst, Wp + (size_t)(n0 + row) * IN_DIM + k0 + c16 * 4);
        }
        CP_COMMIT();
    };

    float acc[2][4][4];
#pragma unroll
    for (int i = 0; i < 2; i++)
#pragma unroll
        for (int j = 0; j < 4; j++)
#pragma unroll
            for (int r = 0; r < 4; r++) acc[i][j][r] = 0.0f;

    load_chunk(0, 0);
    for (int c = 0; c < 8; c++) {
        if (c + 1 < 8) load_chunk(c + 1, (c + 1) & 1);
        if (c + 1 < 8) { CP_WAIT1(); } else { CP_WAIT0(); }
        __syncthreads();
        const int buf = c & 1;
#pragma unroll
        for (int kk = 0; kk < 4; kk++) {
            const int kc = kk * 8 + (lane & 3);
            uint32_t a[2][4], b[4][2];
#pragma unroll
            for (int mt = 0; mt < 2; mt++) {
                int r = mbase + mt * 16 + (lane >> 2);
                a[mt][0] = __float_as_uint(As[buf][r][kc]);
                a[mt][1] = __float_as_uint(As[buf][r + 8][kc]);
                a[mt][2] = __float_as_uint(As[buf][r][kc + 4]);
                a[mt][3] = __float_as_uint(As[buf][r + 8][kc + 4]);
            }
#pragma unroll
            for (int nt = 0; nt < 4; nt++) {
                int n = nbase + nt * 8 + (lane >> 2);
                b[nt][0] = __float_as_uint(Bs[buf][n][kc]);
                b[nt][1] = __float_as_uint(Bs[buf][n][kc + 4]);
            }
#pragma unroll
            for (int mt = 0; mt < 2; mt++)
#pragma unroll
                for (int nt = 0; nt < 4; nt++) mma_tf32_8(acc[mt][nt], a[mt], b[nt]);
        }
        __syncthreads();
    }

#pragma unroll
    for (int mt = 0; mt < 2; mt++) {
        int mA = m0 + mbase + mt * 16 + (lane >> 2);
#pragma unroll
        for (int nt = 0; nt < 4; nt++) {
            int col = n0 + nbase + nt * 8 + (lane & 3) * 2;
            float b0v = bp[col], b1v = bp[col + 1];
            float2 lo, hi;
            lo.x = acc[mt][nt][0] + b0v; lo.y = acc[mt][nt][1] + b1v;
            hi.x = acc[mt][nt][2] + b0v; hi.y = acc[mt][nt][3] + b1v;
            if (g == 2) { lo.x = sigf(lo.x); lo.y = sigf(lo.y); hi.x = sigf(hi.x); hi.y = sigf(hi.y); }
            *(float2*)(outp + (size_t)mA * HID + col) = lo;
            *(float2*)(outp + (size_t)(mA + 8) * HID + col) = hi;
        }
    }
}

// ===================== Persistent recurrence v2 ==============================
// Grid 128 = 4 batch-groups x 32 hidden-groups, 512 threads (16 warps, 4/SMSP).
// Weights resident in SMEM (64 rows x 2048B + 16B pad = 132096B).
// A (c tile) 3 stages x 64 rows x (256B + 16 pad) = 52224B. Total 184320B.
// Warp: gate = wid>>3, w8 = wid&7: M=16 rows (w8>>1)*16, N=16 cols (w8&1)*16.
// K chunk = 128 (8 chunks/step, one __syncthreads each).
// Inter-step sync: bar.sync + tid0 red.release / ld.acquire spin (CG pattern).
#define WROW      2064
#define WSM_BYTES (64 * WROW)                 // 132096
#define AST_BYTES (64 * 272)                  // 17408
#define PS_SMEM   (WSM_BYTES + 3 * AST_BYTES) // 184320

__global__ void __launch_bounds__(512) persist_step()
{
    extern __shared__ __align__(16) char dsm[];
    float (*pre)[64][34] = reinterpret_cast<float(*)[64][34]>(dsm + WSM_BYTES);

    const int tid = threadIdx.x;
    const int wid = tid >> 5, lane = tid & 31;
    const int bgr = blockIdx.x >> 5;        // batch group 0..3
    const int ng  = blockIdx.x & 31;        // hidden group 0..31
    const int b0  = bgr * 64;
    const int n0  = ng * 32;
    const int g   = wid >> 3;               // gate 0/1
    const int w8  = wid & 7;
    const int mrow  = (w8 >> 1) * 16;       // 0,16,32,48
    const int nwarp = (w8 & 1) * 16;

    const uint32_t sW = smem_u32(dsm);
    const uint32_t sA = sW + WSM_BYTES;

    // ---- load weights once: 64 rows (gate*32+hid) x 2048B = 8192 chunks ----
#pragma unroll
    for (int i = 0; i < 16; i++) {
        int ch = tid + i * 512;             // 0..8191
        int row = ch >> 7, c16 = ch & 127;
        const __nv_bfloat16* src = ((row >> 5) ? d_Wih_b : d_Wfh_b)
            + (size_t)(n0 + (row & 31)) * HID + c16 * 8;
        CP16(sW + (uint32_t)row * WROW + (uint32_t)c16 * 16u, src);
    }
    CP_COMMIT(); CP_WAIT0();
    __syncthreads();

    float c_reg[4];
#pragma unroll
    for (int j = 0; j < 4; j++) c_reg[j] = 0.0f;

    const int brow0 = g * 32 + nwarp;
    const uint32_t lquad = lane & 15;
    const uint32_t lhalf = (lane >> 4) * 16u;
    const int em  = tid >> 3;               // epilogue row 0..63
    const int enb = (tid & 7) * 4;          // epilogue col base 0..28

    const uint32_t abase_off = (uint32_t)(mrow + lquad) * 272u + lhalf;
    const uint32_t wbase     = sW + (uint32_t)(brow0 + lquad) * WROW + lhalf;

    for (int t = 0; t < SEQ; t++) {
        const size_t toff = (size_t)t * (NBAT * HID);
        const size_t goff = (size_t)(b0 + em) * HID + n0 + enb;

        // x-part prefetch BEFORE the barrier (independent of c)
        const float4 xf = *(const float4*)(d_xfp + toff + goff);
        const float4 xi = *(const float4*)(d_xip + toff + goff);
        const float4 gv = *(const float4*)(d_g   + toff + goff);

        if (t > 0) {
            if (tid == 0) { while (ld_acq(&d_bar[bgr]) < 32 * t) {} }
            __syncthreads();
        }
        const __nv_bfloat16* __restrict__ cbin  = (t & 1) ? d_cb1 : d_cb0;
        __nv_bfloat16* __restrict__       coutb = (t & 1) ? d_cb0 : d_cb1;

        auto load_chunk = [&](int c, int st) {
            const int k0 = c * 128;
#pragma unroll
            for (int i = 0; i < 2; i++) {
                int ch = tid + i * 512;      // 0..1023
                int row = ch >> 4, c16 = ch & 15;
                CP16(sA + (uint32_t)st * AST_BYTES + (uint32_t)row * 272u + (uint32_t)c16 * 16u,
                     cbin + (size_t)(b0 + row) * HID + k0 + c16 * 8);
            }
            CP_COMMIT();
        };

        float acc[2][4];
#pragma unroll
        for (int j = 0; j < 2; j++)
#pragma unroll
            for (int r = 0; r < 4; r++) acc[j][r] = 0.0f;

        load_chunk(0, 0); load_chunk(1, 1);

#pragma unroll
        for (int c = 0; c < 8; c++) {
            if (c < 7) { CP_WAIT1(); } else { CP_WAIT0(); }
            __syncthreads();                 // stage c ready; stage (c+2)%3 free
            if (c + 2 < 8) load_chunk(c + 2, (c + 2) % 3);

            const uint32_t aC = sA + (uint32_t)(c % 3) * AST_BYTES + abase_off;
            const uint32_t wC = wbase + (uint32_t)c * 256u;
#pragma unroll
            for (int kk = 0; kk < 8; kk++) {
                uint32_t a[4], b[4];
                ldmx4(a, aC + (uint32_t)kk * 32u);
                ldmx4(b, wC + (uint32_t)kk * 32u);
                mma_bf16_16(acc[0], a, b[0], b[2]);
                mma_bf16_16(acc[1], a, b[1], b[3]);
            }
        }
        __syncthreads();   // tile reads done before aliasing pre over A stages

        // stage pre-activations to shared
        {
            int m = mrow + (lane >> 2);
#pragma unroll
            for (int nt = 0; nt < 2; nt++) {
                int n = nwarp + nt * 8 + (lane & 3) * 2;
                pre[g][m][n]         = acc[nt][0];
                pre[g][m][n + 1]     = acc[nt][1];
                pre[g][m + 8][n]     = acc[nt][2];
                pre[g][m + 8][n + 1] = acc[nt][3];
            }
        }
        __syncthreads();

        // pointwise: c_new = g*sig(pre_i + xi) + c*sig(pre_f + xf), c in regs
        {
            const float xfa[4] = { xf.x, xf.y, xf.z, xf.w };
            const float xia[4] = { xi.x, xi.y, xi.z, xi.w };
            const float gva[4] = { gv.x, gv.y, gv.z, gv.w };
            __nv_bfloat16 cb[4];
#pragma unroll
            for (int j = 0; j < 4; j++) {
                float f  = sigf(pre[0][em][enb + j] + xfa[j]);
                float ii = sigf(pre[1][em][enb + j] + xia[j]);
                float cn = gva[j] * ii + c_reg[j] * f;
                c_reg[j] = cn;
                cb[j] = __float2bfloat16_rn(cn);
            }
            *(uint2*)(coutb + goff) = *(const uint2*)cb;     // 4 bf16 = 8B
            if (t >= SEQ - 2) {
                float* cf = (t & 1) ? d_c0 : d_c1;  // t=510 -> d_c1 (c_511), t=511 -> d_c0 (c_512)
                *(float4*)(cf + goff) = make_float4(c_reg[0], c_reg[1], c_reg[2], c_reg[3]);
            }
        }
        __syncthreads();                     // all stores issued before release
        if (t < SEQ - 1 && tid == 0) red_release_add(&d_bar[bgr], 1);
    }
}

// ---------------- final step o-gate + h (fp32 SIMT, tiny) --------------------
__global__ void __launch_bounds__(256) finalO_kernel(
    const int* __restrict__ x, const float* __restrict__ emb,
    const float* __restrict__ Wox, const float* __restrict__ Woh,
    const float* __restrict__ bo)
{
    __shared__ float As[64][33];
    __shared__ float Bs[64][33];
    __shared__ int   idx[64];
    const int tid = threadIdx.x;
    const int n0 = blockIdx.x * 64;
    const int b0 = blockIdx.y * 64;

    if (tid < 64) idx[tid] = x[(b0 + tid) * SEQ + (SEQ - 1)];
    __syncthreads();

    float acc[4][4];
#pragma unroll
    for (int i = 0; i < 4; i++)
#pragma unroll
        for (int j = 0; j < 4; j++) acc[i][j] = 0.0f;

    const int mt = (tid >> 4) * 4;
    const int nt = (tid & 15) * 4;

    for (int k0 = 0; k0 < HID; k0 += 32) {
#pragma unroll
        for (int i = 0; i < 2; i++) {
            int r  = (tid >> 3) + i * 32;
            int kq = (tid & 7) * 4;
            float4 v = *(const float4*)(d_c1 + (size_t)(b0 + r) * HID + k0 + kq);
            As[r][kq+0]=v.x; As[r][kq+1]=v.y; As[r][kq+2]=v.z; As[r][kq+3]=v.w;
            float4 u = *(const float4*)(Woh + (size_t)(n0 + r) * HID + k0 + kq);
            Bs[r][kq+0]=u.x; Bs[r][kq+1]=u.y; Bs[r][kq+2]=u.z; Bs[r][kq+3]=u.w;
        }
        __syncthreads();
#pragma unroll
        for (int k = 0; k < 32; k++) {
            float a[4], bv[4];
#pragma unroll
            for (int i = 0; i < 4; i++) a[i] = As[mt + i][k];
#pragma unroll
            for (int j = 0; j < 4; j++) bv[j] = Bs[nt + j][k];
#pragma unroll
            for (int i = 0; i < 4; i++)
#pragma unroll
                for (int j = 0; j < 4; j++) acc[i][j] += a[i] * bv[j];
        }
        __syncthreads();
    }
    for (int k0 = 0; k0 < IN_DIM; k0 += 32) {
#pragma unroll
        for (int i = 0; i < 2; i++) {
            int r  = (tid >> 3) + i * 32;
            int kq = (tid & 7) * 4;
            float4 v = *(const float4*)(emb + (size_t)idx[r] * IN_DIM + k0 + kq);
            As[r][kq+0]=v.x; As[r][kq+1]=v.y; As[r][kq+2]=v.z; As[r][kq+3]=v.w;
            float4 u = *(const float4*)(Wox + (size_t)(n0 + r) * IN_DIM + k0 + kq);
            Bs[r][kq+0]=u.x; Bs[r][kq+1]=u.y; Bs[r][kq+2]=u.z; Bs[r][kq+3]=u.w;
        }
        __syncthreads();
#pragma unroll
        for (int k = 0; k < 32; k++) {
            float a[4], bv[4];
#pragma unroll
            for (int i = 0; i < 4; i++) a[i] = As[mt + i][k];
#pragma unroll
            for (int j = 0; j < 4; j++) bv[j] = Bs[nt + j][k];
#pragma unroll
            for (int i = 0; i < 4; i++)
#pragma unroll
                for (int j = 0; j < 4; j++) acc[i][j] += a[i] * bv[j];
        }
        __syncthreads();
    }

#pragma unroll
    for (int i = 0; i < 4; i++) {
        int b = b0 + mt + i;
#pragma unroll
        for (int j = 0; j < 4; j++) {
            int h = n0 + nt + j;
            size_t off = (size_t)b * HID + h;
            float o = sigf(acc[i][j] + bo[h]);
            d_hT[off] = tanhf(d_c0[off]) * o;
        }
    }
}

// ---------------- projection + log_softmax ----------------------------------
__global__ void __launch_bounds__(128) proj_kernel(
    const float* __restrict__ Wph, const float* __restrict__ bp,
    float* __restrict__ out)
{
    const int b = blockIdx.x;
    const int n = threadIdx.x;
    __shared__ float hs[HID];
    for (int k = n; k < HID; k += 128) hs[k] = d_hT[(size_t)b * HID + k];
    __syncthreads();

    const float* w = Wph + (size_t)n * HID;
    float acc = bp[n];
#pragma unroll 8
    for (int k = 0; k < HID; k++) acc += hs[k] * w[k];

    __shared__ float red[128];
    red[n] = acc;
    __syncthreads();
    for (int off = 64; off > 0; off >>= 1) {
        if (n < off) red[n] = fmaxf(red[n], red[n + off]);
        __syncthreads();
    }
    float mx = red[0];
    __syncthreads();
    red[n] = __expf(acc - mx);
    __syncthreads();
    for (int off = 64; off > 0; off >>= 1) {
        if (n < off) red[n] += red[n + off];
        __syncthreads();
    }
    float lse = mx + logf(red[0]);
    out[(size_t)b * NCLS + n] = acc - lse;
}

// ---------------- launch ------------------------------------------------------
extern "C" void kernel_launch(void* const* d_in, const int* in_sizes, int n_in,
                              void* d_out, int out_size)
{
    (void)in_sizes; (void)n_in; (void)out_size;
    const int*   x   = (const int*)  d_in[0];
    const float* emb = (const float*)d_in[1];
    const float* Wcx = (const float*)d_in[2];
    const float* bc  = (const float*)d_in[3];
    const float* Wix = (const float*)d_in[4];
    const float* Wih = (const float*)d_in[5];
    const float* bi  = (const float*)d_in[6];
    const float* Wfx = (const float*)d_in[7];
    const float* Wfh = (const float*)d_in[8];
    const float* bf  = (const float*)d_in[9];
    const float* Wox = (const float*)d_in[10];
    const float* Woh = (const float*)d_in[11];
    const float* bo  = (const float*)d_in[12];
    const float* Wph = (const float*)d_in[13];
    const float* bp  = (const float*)d_in[14];
    float* out = (float*)d_out;

    cudaFuncSetAttribute(phaseA_mma, cudaFuncAttributeMaxDynamicSharedMemorySize, PA_SMEM);
    cudaFuncSetAttribute(persist_step, cudaFuncAttributeMaxDynamicSharedMemorySize, PS_SMEM);

    round_all<<<11392, 256>>>(Wfh, Wih, Wfx, Wix, Wcx, emb);

    phaseA_mma<<<dim3(SEQ * NBAT / 128, HID / 64, 3), 256, PA_SMEM>>>(x, bf, bi, bc);
    zero_c_kernel<<<NBAT * HID / 256, 256>>>();

    persist_step<<<128, 512, PS_SMEM>>>();

    finalO_kernel<<<dim3(HID / 64, NBAT / 64), 256>>>(x, emb, Wox, Woh, bo);
    proj_kernel<<<NBAT, 128>>>(Wph, bp, out);
}